// round 6
// baseline (speedup 1.0000x reference)
#include <cuda_runtime.h>
#include <cuda_bf16.h>

#define T_SEQ 34
#define NTOK  14
#define NE    476   // 34*14 distinct (position, token) variants

typedef unsigned long long u64;
typedef unsigned int       u32;

// LUTs built by prologue kernel (device globals: no allocation allowed)
__device__ float2 g_q[NE * 3];   // prescaled q, packed (head0, head1) per dim
__device__ u64    g_kv[NE * 4];  // bf16x4 per u64, padded to 32B/entry for LDS.128
__device__ float2 g_x[NE * 3];   // raw embedded x (pre-LN), for residual

// ---------- packed f32x2 helpers (sm_103a) ----------
__device__ __forceinline__ u64 pk2(float a, float b) {
    u64 r; asm("mov.b64 %0,{%1,%2};" : "=l"(r) : "f"(a), "f"(b)); return r;
}
__device__ __forceinline__ u64 pk2f(float2 f) { return pk2(f.x, f.y); }
__device__ __forceinline__ float2 upk2(u64 v) {
    float2 f; asm("mov.b64 {%0,%1},%2;" : "=f"(f.x), "=f"(f.y) : "l"(v)); return f;
}
__device__ __forceinline__ u64 rep2(float a) {
    u64 r; asm("mov.b64 %0,{%1,%1};" : "=l"(r) : "f"(a)); return r;
}
__device__ __forceinline__ u64 fma2(u64 a, u64 b, u64 c) {
    u64 d; asm("fma.rn.f32x2 %0,%1,%2,%3;" : "=l"(d) : "l"(a), "l"(b), "l"(c)); return d;
}
__device__ __forceinline__ u64 add2(u64 a, u64 b) {
    u64 d; asm("add.rn.f32x2 %0,%1,%2;" : "=l"(d) : "l"(a), "l"(b)); return d;
}
__device__ __forceinline__ u64 mul2(u64 a, u64 b) {
    u64 d; asm("mul.rn.f32x2 %0,%1,%2;" : "=l"(d) : "l"(a), "l"(b)); return d;
}
// bf16x2 (lo=head0, hi=head1) -> f32x2
__device__ __forceinline__ u64 bfpair(u32 u) {
    u32 lo = u << 16, hi = u & 0xffff0000u;
    u64 r; asm("mov.b64 %0,{%1,%2};" : "=l"(r) : "r"(lo), "r"(hi)); return r;
}
__device__ __forceinline__ float fex2(float x) { float r; asm("ex2.approx.f32 %0,%1;" : "=f"(r) : "f"(x)); return r; }
__device__ __forceinline__ float frcp(float x) { float r; asm("rcp.approx.f32 %0,%1;" : "=f"(r) : "f"(x)); return r; }
__device__ __forceinline__ float frsq(float x) { float r; asm("rsqrt.approx.f32 %0,%1;" : "=f"(r) : "f"(x)); return r; }

__device__ __forceinline__ unsigned short bfb(float f) {
    return __bfloat16_as_ushort(__float2bfloat16_rn(f));
}

// ---------- prologue: build 476-entry LUTs ----------
__global__ void build_luts(const float* __restrict__ tok_emb, const float* __restrict__ pos_enc,
                           const float* __restrict__ wq, const float* __restrict__ wk,
                           const float* __restrict__ wv,
                           const float* __restrict__ g1, const float* __restrict__ b1) {
    int e = blockIdx.x * blockDim.x + threadIdx.x;
    if (e >= NE) return;
    int t = e / NTOK, c = e % NTOK;
    float x[6];
    x[0] = tok_emb[c * 3 + 0]; x[1] = tok_emb[c * 3 + 1]; x[2] = tok_emb[c * 3 + 2];
    x[3] = pos_enc[t * 3 + 0]; x[4] = pos_enc[t * 3 + 1]; x[5] = pos_enc[t * 3 + 2];
    float s = 0.f;
#pragma unroll
    for (int i = 0; i < 6; i++) s += x[i];
    float mu = s * (1.f / 6.f);
    float v = 0.f;
#pragma unroll
    for (int i = 0; i < 6; i++) { float d = x[i] - mu; v += d * d; }
    v *= (1.f / 6.f);
    float r = frsq(v + 1e-5f);
    float n[6];
#pragma unroll
    for (int i = 0; i < 6; i++) n[i] = (x[i] - mu) * r * g1[i] + b1[i];

    float q[6], k[6], vv[6];  // index = h*3+d
#pragma unroll
    for (int j = 0; j < 6; j++) {
        q[j]  = n[3] * wq[j] + n[4] * wq[6 + j] + n[5] * wq[12 + j];
        k[j]  = n[3] * wk[j] + n[4] * wk[6 + j] + n[5] * wk[12 + j];
        vv[j] = n[0] * wv[j] + n[1] * wv[6 + j] + n[2] * wv[12 + j];
    }
    // fold 1/sqrt(HEAD_DIM) and log2(e) into q (inner loop uses ex2)
    const float qs = 1.4426950408889634f * 0.57735026918962576f;
    float2* qp = g_q + e * 3;
#pragma unroll
    for (int d = 0; d < 3; d++) qp[d] = make_float2(q[d] * qs, q[3 + d] * qs);

    u32 w[6];
#pragma unroll
    for (int d = 0; d < 3; d++) {
        w[d]     = ((u32)bfb(k[3 + d])  << 16) | (u32)bfb(k[d]);
        w[3 + d] = ((u32)bfb(vv[3 + d]) << 16) | (u32)bfb(vv[d]);
    }
    u64* kvp = g_kv + e * 4;
    kvp[0] = ((u64)w[1] << 32) | w[0];
    kvp[1] = ((u64)w[3] << 32) | w[2];
    kvp[2] = ((u64)w[5] << 32) | w[4];
    kvp[3] = 0;

    float2* xp = g_x + e * 3;
    xp[0] = make_float2(x[0], x[1]);
    xp[1] = make_float2(x[2], x[3]);
    xp[2] = make_float2(x[4], x[5]);
}

// ---------- per-token layernorm over 6 dims ----------
__device__ __forceinline__ void ln6(const float* x, float* o, const float* g, const float* b) {
    float s = 0.f;
#pragma unroll
    for (int i = 0; i < 6; i++) s += x[i];
    float mu = s * (1.f / 6.f);
    float v = 0.f;
#pragma unroll
    for (int i = 0; i < 6; i++) { float d = x[i] - mu; v += d * d; }
    v *= (1.f / 6.f);
    float r = frsq(v + 1e-5f);
#pragma unroll
    for (int i = 0; i < 6; i++) o[i] = (x[i] - mu) * r * g[i] + b[i];
}

__device__ __forceinline__ float gelu_exact(float x) {
    return 0.5f * x * (1.f + erff(x * 0.70710678118654752f));
}

// ---------- per-token epilogue (weights re-read via broadcast LDS) ----------
__device__ __forceinline__ void epi_token(const float* __restrict__ o,
                                          const float2* __restrict__ xr,
                                          const float* __restrict__ sw,
                                          float* __restrict__ outp) {
    const u64* woP = (const u64*)sw;            // rows j: woP[j*4 + p], p<3
    const u64* w1P = (const u64*)(sw + 48);
    const u64* w2P = (const u64*)(sw + 96);
    const u64* whP = (const u64*)(sw + 144);    // rows i: whP[i*8 + p], p<7
    const u64* b1P = (const u64*)(sw + 240);
    const u64* b2P = (const u64*)(sw + 248);

    // residual + attention out projection
    u64 x1[3] = { pk2f(xr[0]), pk2f(xr[1]), pk2f(xr[2]) };
#pragma unroll
    for (int j = 0; j < 6; j++) {
        u64 oa = rep2(o[j]);
        x1[0] = fma2(oa, woP[j * 4],     x1[0]);
        x1[1] = fma2(oa, woP[j * 4 + 1], x1[1]);
        x1[2] = fma2(oa, woP[j * 4 + 2], x1[2]);
    }
    float xa[6];
#pragma unroll
    for (int p = 0; p < 3; p++) { float2 f = upk2(x1[p]); xa[2 * p] = f.x; xa[2 * p + 1] = f.y; }

    float ha[6];
    ln6(xa, ha, sw + 256, sw + 264);

    u64 ff[3] = { b1P[0], b1P[1], b1P[2] };
#pragma unroll
    for (int i = 0; i < 6; i++) {
        u64 va = rep2(ha[i]);
        ff[0] = fma2(va, w1P[i * 4],     ff[0]);
        ff[1] = fma2(va, w1P[i * 4 + 1], ff[1]);
        ff[2] = fma2(va, w1P[i * 4 + 2], ff[2]);
    }
    float g[6];
#pragma unroll
    for (int p = 0; p < 3; p++) {
        float2 f = upk2(ff[p]);
        g[2 * p] = gelu_exact(f.x); g[2 * p + 1] = gelu_exact(f.y);
    }
    u64 x2[3];
#pragma unroll
    for (int p = 0; p < 3; p++) x2[p] = add2(x1[p], b2P[p]);
#pragma unroll
    for (int j = 0; j < 6; j++) {
        u64 va = rep2(g[j]);
        x2[0] = fma2(va, w2P[j * 4],     x2[0]);
        x2[1] = fma2(va, w2P[j * 4 + 1], x2[1]);
        x2[2] = fma2(va, w2P[j * 4 + 2], x2[2]);
    }
    float ta[6], ya[6];
#pragma unroll
    for (int p = 0; p < 3; p++) { float2 f = upk2(x2[p]); ta[2 * p] = f.x; ta[2 * p + 1] = f.y; }
    ln6(ta, ya, sw + 272, sw + 280);

    u64 la[7] = {0, 0, 0, 0, 0, 0, 0};
#pragma unroll
    for (int i = 0; i < 6; i++) {
        u64 va = rep2(ya[i]);
#pragma unroll
        for (int p = 0; p < 7; p++) la[p] = fma2(va, whP[i * 8 + p], la[p]);
    }
    u64* op = (u64*)outp;
#pragma unroll
    for (int p = 0; p < 7; p++) op[p] = la[p];
}

// ---------- one token pair {t1, t2=33-t1}: fused attention loop + epilogues ----------
__device__ __forceinline__ void attn_pair(int t1, int t2, int lane, int seq,
                                          const float2* __restrict__ sh_q,
                                          const u64* __restrict__ sh_kv,
                                          const float2* __restrict__ sh_x,
                                          const int* __restrict__ sh_off,
                                          const float* __restrict__ sw,
                                          float* __restrict__ out) {
    int e1 = sh_off[t1 * 32 + lane] >> 2;
    int e2 = sh_off[t2 * 32 + lane] >> 2;

    u64 q1[3], q2v[3];
    {
        const float2* p = sh_q + e1 * 3;
        q1[0] = pk2f(p[0]); q1[1] = pk2f(p[1]); q1[2] = pk2f(p[2]);
        const float2* r = sh_q + e2 * 3;
        q2v[0] = pk2f(r[0]); q2v[1] = pk2f(r[1]); q2v[2] = pk2f(r[2]);
    }

    u64 acc1[3] = {0, 0, 0}, acc2[3] = {0, 0, 0};
    u64 den1 = 0, den2 = 0;   // packed (0.f,0.f)

#pragma unroll 2
    for (int k = 0; k <= t2; k++) {
        int o4 = sh_off[k * 32 + lane];
        ulonglong2 kvA = *(const ulonglong2*)(sh_kv + o4);   // LDS.128 (32B-aligned)
        u64 kv2 = sh_kv[o4 + 2];                             // LDS.64
        u64 K0 = bfpair((u32)kvA.x), K1 = bfpair((u32)(kvA.x >> 32)), K2 = bfpair((u32)kvA.y);
        u64 V0 = bfpair((u32)(kvA.y >> 32)), V1 = bfpair((u32)kv2), V2 = bfpair((u32)(kv2 >> 32));

        u64 s2 = fma2(q2v[0], K0, fma2(q2v[1], K1, mul2(q2v[2], K2)));
        float2 sf = upk2(s2);
        u64 w2p = pk2(fex2(sf.x), fex2(sf.y));
        den2 = add2(den2, w2p);
        acc2[0] = fma2(w2p, V0, acc2[0]);
        acc2[1] = fma2(w2p, V1, acc2[1]);
        acc2[2] = fma2(w2p, V2, acc2[2]);

        if (k <= t1) {   // prefix of the same loop: shared K/V reads
            u64 s1 = fma2(q1[0], K0, fma2(q1[1], K1, mul2(q1[2], K2)));
            float2 s1f = upk2(s1);
            u64 w1p = pk2(fex2(s1f.x), fex2(s1f.y));
            den1 = add2(den1, w1p);
            acc1[0] = fma2(w1p, V0, acc1[0]);
            acc1[1] = fma2(w1p, V1, acc1[1]);
            acc1[2] = fma2(w1p, V2, acc1[2]);
        }
    }

    float o1[6], o2[6];   // [h*3+d]
    {
        float2 d1 = upk2(den1); float r0 = frcp(d1.x), r1 = frcp(d1.y);
#pragma unroll
        for (int d = 0; d < 3; d++) { float2 a = upk2(acc1[d]); o1[d] = a.x * r0; o1[3 + d] = a.y * r1; }
        float2 d2 = upk2(den2); float s0 = frcp(d2.x), s1 = frcp(d2.y);
#pragma unroll
        for (int d = 0; d < 3; d++) { float2 a = upk2(acc2[d]); o2[d] = a.x * s0; o2[3 + d] = a.y * s1; }
    }

    epi_token(o1, sh_x + e1 * 3, sw, out + (seq * 34 + t1) * 14);
    epi_token(o2, sh_x + e2 * 3, sw, out + (seq * 34 + t2) * 14);
}

// ---------- main kernel: 32 sequences/block, 16 warps, warp y does pair {y,33-y};
//            warp 15 additionally does pair {16,17}. 2 CTAs/SM (64-reg cap). ----------
__global__ void __launch_bounds__(512, 2)
tf_main(const int* __restrict__ idx, float* __restrict__ out,
        const float* __restrict__ wo, const float* __restrict__ g2, const float* __restrict__ bb2,
        const float* __restrict__ w1, const float* __restrict__ b1v,
        const float* __restrict__ w2, const float* __restrict__ b2v,
        const float* __restrict__ gf, const float* __restrict__ bfv,
        const float* __restrict__ wh) {
    __shared__ float2 sh_q[NE * 3];
    __shared__ u64    sh_kv[NE * 4];
    __shared__ float2 sh_x[NE * 3];
    __shared__ int    sh_off[T_SEQ * 32];
    __shared__ __align__(16) float sw[288];

    const int NT = 512;
    int tid = threadIdx.y * 32 + threadIdx.x;
    int base = blockIdx.x * 32;

    for (int i = tid; i < NE * 3; i += NT) {
        sh_q[i] = g_q[i];
        sh_x[i] = g_x[i];
    }
    for (int i = tid; i < NE * 4; i += NT) sh_kv[i] = g_kv[i];
    for (int i = tid; i < 288; i += NT) sw[i] = 0.f;
    for (int i = tid; i < T_SEQ * 32; i += NT) {
        int k = i >> 5, ln = i & 31;
        sh_off[i] = (k * NTOK + idx[(base + ln) * T_SEQ + k]) * 4;  // u64-index into sh_kv
    }
    __syncthreads();
    // structured weight fill (padding already zeroed)
    if (tid < 36)       { sw[(tid / 6) * 8 + tid % 6] = wo[tid]; }
    else if (tid < 72)  { int i = tid - 36;  sw[48  + (i / 6) * 8  + i % 6]  = w1[i]; }
    else if (tid < 108) { int i = tid - 72;  sw[96  + (i / 6) * 8  + i % 6]  = w2[i]; }
    else if (tid < 192) { int i = tid - 108; sw[144 + (i / 14) * 16 + i % 14] = wh[i]; }
    else if (tid < 198) { sw[240 + tid - 192] = b1v[tid - 192]; }
    else if (tid < 204) { sw[248 + tid - 198] = b2v[tid - 198]; }
    else if (tid < 210) { sw[256 + tid - 204] = g2[tid - 204]; }
    else if (tid < 216) { sw[264 + tid - 210] = bb2[tid - 210]; }
    else if (tid < 222) { sw[272 + tid - 216] = gf[tid - 216]; }
    else if (tid < 228) { sw[280 + tid - 222] = bfv[tid - 222]; }
    __syncthreads();

    int lane = threadIdx.x, y = threadIdx.y;
    int seq = base + lane;

    attn_pair(y, 33 - y, lane, seq, sh_q, sh_kv, sh_x, sh_off, sw, out);
    if (y == 15)   // 17th pair, middle (shortest loops)
        attn_pair(16, 17, lane, seq, sh_q, sh_kv, sh_x, sh_off, sw, out);
}

extern "C" void kernel_launch(void* const* d_in, const int* in_sizes, int n_in,
                              void* d_out, int out_size) {
    const int*   idx     = (const int*)d_in[0];
    const float* tok_emb = (const float*)d_in[1];
    const float* pos_enc = (const float*)d_in[2];
    const float* wq      = (const float*)d_in[3];
    const float* wk      = (const float*)d_in[4];
    const float* wv      = (const float*)d_in[5];
    const float* wo      = (const float*)d_in[6];
    const float* ln1_g   = (const float*)d_in[7];
    const float* ln1_b   = (const float*)d_in[8];
    const float* ln2_g   = (const float*)d_in[9];
    const float* ln2_b   = (const float*)d_in[10];
    const float* w1      = (const float*)d_in[11];
    const float* b1      = (const float*)d_in[12];
    const float* w2      = (const float*)d_in[13];
    const float* b2      = (const float*)d_in[14];
    const float* lnf_g   = (const float*)d_in[15];
    const float* lnf_b   = (const float*)d_in[16];
    const float* wh      = (const float*)d_in[17];

    int nseq = in_sizes[0] / T_SEQ;
    build_luts<<<1, 512>>>(tok_emb, pos_enc, wq, wk, wv, ln1_g, ln1_b);
    dim3 blk(32, 16);
    tf_main<<<nseq / 32, blk>>>(idx, (float*)d_out, wo, ln2_g, ln2_b,
                                w1, b1, w2, b2, lnf_g, lnf_b, wh);
}

// round 8
// speedup vs baseline: 2.0422x; 2.0422x over previous
#include <cuda_runtime.h>
#include <cuda_bf16.h>

#define T_SEQ 34
#define NTOK  14
#define NE    476   // 34*14 distinct (position, token) variants

typedef unsigned long long u64;
typedef unsigned int       u32;

// LUTs built by prologue kernel (device globals: no allocation allowed)
__device__ float2 g_q[NE * 3];   // prescaled q, packed (head0, head1) per dim
__device__ u64    g_kv[NE * 4];  // bf16x4 per u64, padded to 32B/entry for LDS.128
__device__ float2 g_x[NE * 3];   // raw embedded x (pre-LN), for residual

// ---------- packed f32x2 helpers (sm_103a) ----------
__device__ __forceinline__ u64 pk2(float a, float b) {
    u64 r; asm("mov.b64 %0,{%1,%2};" : "=l"(r) : "f"(a), "f"(b)); return r;
}
__device__ __forceinline__ u64 pk2f(float2 f) { return pk2(f.x, f.y); }
__device__ __forceinline__ float2 upk2(u64 v) {
    float2 f; asm("mov.b64 {%0,%1},%2;" : "=f"(f.x), "=f"(f.y) : "l"(v)); return f;
}
__device__ __forceinline__ u64 rep2(float a) {
    u64 r; asm("mov.b64 %0,{%1,%1};" : "=l"(r) : "f"(a)); return r;
}
__device__ __forceinline__ u64 fma2(u64 a, u64 b, u64 c) {
    u64 d; asm("fma.rn.f32x2 %0,%1,%2,%3;" : "=l"(d) : "l"(a), "l"(b), "l"(c)); return d;
}
__device__ __forceinline__ u64 add2(u64 a, u64 b) {
    u64 d; asm("add.rn.f32x2 %0,%1,%2;" : "=l"(d) : "l"(a), "l"(b)); return d;
}
__device__ __forceinline__ u64 mul2(u64 a, u64 b) {
    u64 d; asm("mul.rn.f32x2 %0,%1,%2;" : "=l"(d) : "l"(a), "l"(b)); return d;
}
// bf16x2 (lo=head0, hi=head1) -> f32x2
__device__ __forceinline__ u64 bfpair(u32 u) {
    u32 lo = u << 16, hi = u & 0xffff0000u;
    u64 r; asm("mov.b64 %0,{%1,%2};" : "=l"(r) : "r"(lo), "r"(hi)); return r;
}
__device__ __forceinline__ float fex2(float x) { float r; asm("ex2.approx.f32 %0,%1;" : "=f"(r) : "f"(x)); return r; }
__device__ __forceinline__ float frcp(float x) { float r; asm("rcp.approx.f32 %0,%1;" : "=f"(r) : "f"(x)); return r; }
__device__ __forceinline__ float frsq(float x) { float r; asm("rsqrt.approx.f32 %0,%1;" : "=f"(r) : "f"(x)); return r; }

__device__ __forceinline__ unsigned short bfb(float f) {
    return __bfloat16_as_ushort(__float2bfloat16_rn(f));
}

// ---------- prologue: build 476-entry LUTs ----------
__global__ void build_luts(const float* __restrict__ tok_emb, const float* __restrict__ pos_enc,
                           const float* __restrict__ wq, const float* __restrict__ wk,
                           const float* __restrict__ wv,
                           const float* __restrict__ g1, const float* __restrict__ b1) {
    int e = blockIdx.x * blockDim.x + threadIdx.x;
    if (e >= NE) return;
    int t = e / NTOK, c = e % NTOK;
    float x[6];
    x[0] = tok_emb[c * 3 + 0]; x[1] = tok_emb[c * 3 + 1]; x[2] = tok_emb[c * 3 + 2];
    x[3] = pos_enc[t * 3 + 0]; x[4] = pos_enc[t * 3 + 1]; x[5] = pos_enc[t * 3 + 2];
    float s = 0.f;
#pragma unroll
    for (int i = 0; i < 6; i++) s += x[i];
    float mu = s * (1.f / 6.f);
    float v = 0.f;
#pragma unroll
    for (int i = 0; i < 6; i++) { float d = x[i] - mu; v += d * d; }
    v *= (1.f / 6.f);
    float r = frsq(v + 1e-5f);
    float n[6];
#pragma unroll
    for (int i = 0; i < 6; i++) n[i] = (x[i] - mu) * r * g1[i] + b1[i];

    float q[6], k[6], vv[6];  // index = h*3+d
#pragma unroll
    for (int j = 0; j < 6; j++) {
        q[j]  = n[3] * wq[j] + n[4] * wq[6 + j] + n[5] * wq[12 + j];
        k[j]  = n[3] * wk[j] + n[4] * wk[6 + j] + n[5] * wk[12 + j];
        vv[j] = n[0] * wv[j] + n[1] * wv[6 + j] + n[2] * wv[12 + j];
    }
    // fold 1/sqrt(HEAD_DIM) and log2(e) into q (inner loop uses ex2)
    const float qs = 1.4426950408889634f * 0.57735026918962576f;
    float2* qp = g_q + e * 3;
#pragma unroll
    for (int d = 0; d < 3; d++) qp[d] = make_float2(q[d] * qs, q[3 + d] * qs);

    u32 w[6];
#pragma unroll
    for (int d = 0; d < 3; d++) {
        w[d]     = ((u32)bfb(k[3 + d])  << 16) | (u32)bfb(k[d]);
        w[3 + d] = ((u32)bfb(vv[3 + d]) << 16) | (u32)bfb(vv[d]);
    }
    u64* kvp = g_kv + e * 4;
    kvp[0] = ((u64)w[1] << 32) | w[0];
    kvp[1] = ((u64)w[3] << 32) | w[2];
    kvp[2] = ((u64)w[5] << 32) | w[4];
    kvp[3] = 0;

    float2* xp = g_x + e * 3;
    xp[0] = make_float2(x[0], x[1]);
    xp[1] = make_float2(x[2], x[3]);
    xp[2] = make_float2(x[4], x[5]);
}

// ---------- per-token layernorm over 6 dims ----------
__device__ __forceinline__ void ln6(const float* x, float* o, const float* g, const float* b) {
    float s = 0.f;
#pragma unroll
    for (int i = 0; i < 6; i++) s += x[i];
    float mu = s * (1.f / 6.f);
    float v = 0.f;
#pragma unroll
    for (int i = 0; i < 6; i++) { float d = x[i] - mu; v += d * d; }
    v *= (1.f / 6.f);
    float r = frsq(v + 1e-5f);
#pragma unroll
    for (int i = 0; i < 6; i++) o[i] = (x[i] - mu) * r * g[i] + b[i];
}

__device__ __forceinline__ float gelu_exact(float x) {
    return 0.5f * x * (1.f + erff(x * 0.70710678118654752f));
}

// ---------- per-token epilogue (weights re-read via broadcast LDS) ----------
__device__ __forceinline__ void epi_token(const float* __restrict__ o,
                                          const float2* __restrict__ xr,
                                          const float* __restrict__ sw,
                                          float* __restrict__ outp) {
    const u64* woP = (const u64*)sw;            // rows j: woP[j*4 + p], p<3
    const u64* w1P = (const u64*)(sw + 48);
    const u64* w2P = (const u64*)(sw + 96);
    const u64* whP = (const u64*)(sw + 144);    // rows i: whP[i*8 + p], p<7
    const u64* b1P = (const u64*)(sw + 240);
    const u64* b2P = (const u64*)(sw + 248);

    // residual + attention out projection
    u64 x1[3] = { pk2f(xr[0]), pk2f(xr[1]), pk2f(xr[2]) };
#pragma unroll
    for (int j = 0; j < 6; j++) {
        u64 oa = rep2(o[j]);
        x1[0] = fma2(oa, woP[j * 4],     x1[0]);
        x1[1] = fma2(oa, woP[j * 4 + 1], x1[1]);
        x1[2] = fma2(oa, woP[j * 4 + 2], x1[2]);
    }
    float xa[6];
#pragma unroll
    for (int p = 0; p < 3; p++) { float2 f = upk2(x1[p]); xa[2 * p] = f.x; xa[2 * p + 1] = f.y; }

    float ha[6];
    ln6(xa, ha, sw + 256, sw + 264);

    u64 ff[3] = { b1P[0], b1P[1], b1P[2] };
#pragma unroll
    for (int i = 0; i < 6; i++) {
        u64 va = rep2(ha[i]);
        ff[0] = fma2(va, w1P[i * 4],     ff[0]);
        ff[1] = fma2(va, w1P[i * 4 + 1], ff[1]);
        ff[2] = fma2(va, w1P[i * 4 + 2], ff[2]);
    }
    float g[6];
#pragma unroll
    for (int p = 0; p < 3; p++) {
        float2 f = upk2(ff[p]);
        g[2 * p] = gelu_exact(f.x); g[2 * p + 1] = gelu_exact(f.y);
    }
    u64 x2[3];
#pragma unroll
    for (int p = 0; p < 3; p++) x2[p] = add2(x1[p], b2P[p]);
#pragma unroll
    for (int j = 0; j < 6; j++) {
        u64 va = rep2(g[j]);
        x2[0] = fma2(va, w2P[j * 4],     x2[0]);
        x2[1] = fma2(va, w2P[j * 4 + 1], x2[1]);
        x2[2] = fma2(va, w2P[j * 4 + 2], x2[2]);
    }
    float ta[6], ya[6];
#pragma unroll
    for (int p = 0; p < 3; p++) { float2 f = upk2(x2[p]); ta[2 * p] = f.x; ta[2 * p + 1] = f.y; }
    ln6(ta, ya, sw + 272, sw + 280);

    u64 la[7] = {0, 0, 0, 0, 0, 0, 0};
#pragma unroll
    for (int i = 0; i < 6; i++) {
        u64 va = rep2(ya[i]);
#pragma unroll
        for (int p = 0; p < 7; p++) la[p] = fma2(va, whP[i * 8 + p], la[p]);
    }
    u64* op = (u64*)outp;
#pragma unroll
    for (int p = 0; p < 7; p++) op[p] = la[p];
}

// ---------- ONE token end-to-end (low register footprint: ~40 live regs) ----------
__device__ __forceinline__ void attn_one(int t, int lane, int seq,
                                         const float2* __restrict__ sh_q,
                                         const u64* __restrict__ sh_kv,
                                         const float2* __restrict__ sh_x,
                                         const int* __restrict__ sh_off,
                                         const float* __restrict__ sw,
                                         float* __restrict__ out) {
    int e = sh_off[t * 32 + lane] >> 2;

    u64 q[3];
    {
        const float2* p = sh_q + e * 3;
        q[0] = pk2f(p[0]); q[1] = pk2f(p[1]); q[2] = pk2f(p[2]);
    }

    u64 acc[3] = {0, 0, 0};
    u64 den = 0;   // packed (0.f,0.f)

#pragma unroll 2
    for (int k = 0; k <= t; k++) {
        int o4 = sh_off[k * 32 + lane];
        ulonglong2 kvA = *(const ulonglong2*)(sh_kv + o4);   // LDS.128 (32B-aligned)
        u64 kv2 = sh_kv[o4 + 2];                             // LDS.64
        u64 K0 = bfpair((u32)kvA.x), K1 = bfpair((u32)(kvA.x >> 32)), K2 = bfpair((u32)kvA.y);
        u64 V0 = bfpair((u32)(kvA.y >> 32)), V1 = bfpair((u32)kv2), V2 = bfpair((u32)(kv2 >> 32));

        u64 s = fma2(q[0], K0, fma2(q[1], K1, mul2(q[2], K2)));
        float2 sf = upk2(s);
        u64 w = pk2(fex2(sf.x), fex2(sf.y));
        den = add2(den, w);
        acc[0] = fma2(w, V0, acc[0]);
        acc[1] = fma2(w, V1, acc[1]);
        acc[2] = fma2(w, V2, acc[2]);
    }

    float o[6];   // [h*3+d]
    {
        float2 d = upk2(den); float r0 = frcp(d.x), r1 = frcp(d.y);
#pragma unroll
        for (int j = 0; j < 3; j++) { float2 a = upk2(acc[j]); o[j] = a.x * r0; o[3 + j] = a.y * r1; }
    }

    epi_token(o, sh_x + e * 3, sw, out + (seq * 34 + t) * 14);
}

// ---------- main kernel: 32 sequences/block, 17 warps, warp y does t=y then t=33-y;
//            sequential tokens keep live state ~40 regs -> 2 CTAs/SM without spills ----------
__global__ void __launch_bounds__(544, 2)
tf_main(const int* __restrict__ idx, float* __restrict__ out,
        const float* __restrict__ wo, const float* __restrict__ g2, const float* __restrict__ bb2,
        const float* __restrict__ w1, const float* __restrict__ b1v,
        const float* __restrict__ w2, const float* __restrict__ b2v,
        const float* __restrict__ gf, const float* __restrict__ bfv,
        const float* __restrict__ wh) {
    __shared__ float2 sh_q[NE * 3];
    __shared__ u64    sh_kv[NE * 4];
    __shared__ float2 sh_x[NE * 3];
    __shared__ int    sh_off[T_SEQ * 32];
    __shared__ __align__(16) float sw[288];

    const int NT = 544;
    int tid = threadIdx.y * 32 + threadIdx.x;
    int base = blockIdx.x * 32;

    for (int i = tid; i < NE * 3; i += NT) {
        sh_q[i] = g_q[i];
        sh_x[i] = g_x[i];
    }
    for (int i = tid; i < NE * 4; i += NT) sh_kv[i] = g_kv[i];
    for (int i = tid; i < 288; i += NT) sw[i] = 0.f;
    for (int i = tid; i < T_SEQ * 32; i += NT) {
        int k = i >> 5, ln = i & 31;
        sh_off[i] = (k * NTOK + idx[(base + ln) * T_SEQ + k]) * 4;  // u64-index into sh_kv
    }
    __syncthreads();
    // structured weight fill (padding already zeroed)
    if (tid < 36)       { sw[(tid / 6) * 8 + tid % 6] = wo[tid]; }
    else if (tid < 72)  { int i = tid - 36;  sw[48  + (i / 6) * 8  + i % 6]  = w1[i]; }
    else if (tid < 108) { int i = tid - 72;  sw[96  + (i / 6) * 8  + i % 6]  = w2[i]; }
    else if (tid < 192) { int i = tid - 108; sw[144 + (i / 14) * 16 + i % 14] = wh[i]; }
    else if (tid < 198) { sw[240 + tid - 192] = b1v[tid - 192]; }
    else if (tid < 204) { sw[248 + tid - 198] = b2v[tid - 198]; }
    else if (tid < 210) { sw[256 + tid - 204] = g2[tid - 204]; }
    else if (tid < 216) { sw[264 + tid - 210] = bb2[tid - 210]; }
    else if (tid < 222) { sw[272 + tid - 216] = gf[tid - 216]; }
    else if (tid < 228) { sw[280 + tid - 222] = bfv[tid - 222]; }
    __syncthreads();

    int lane = threadIdx.x, y = threadIdx.y;
    int seq = base + lane;

    attn_one(y, lane, seq, sh_q, sh_kv, sh_x, sh_off, sw, out);
    __syncwarp();   // keep token-2 state out of token-1's live range
    attn_one(33 - y, lane, seq, sh_q, sh_kv, sh_x, sh_off, sw, out);
}

extern "C" void kernel_launch(void* const* d_in, const int* in_sizes, int n_in,
                              void* d_out, int out_size) {
    const int*   idx     = (const int*)d_in[0];
    const float* tok_emb = (const float*)d_in[1];
    const float* pos_enc = (const float*)d_in[2];
    const float* wq      = (const float*)d_in[3];
    const float* wk      = (const float*)d_in[4];
    const float* wv      = (const float*)d_in[5];
    const float* wo      = (const float*)d_in[6];
    const float* ln1_g   = (const float*)d_in[7];
    const float* ln1_b   = (const float*)d_in[8];
    const float* ln2_g   = (const float*)d_in[9];
    const float* ln2_b   = (const float*)d_in[10];
    const float* w1      = (const float*)d_in[11];
    const float* b1      = (const float*)d_in[12];
    const float* w2      = (const float*)d_in[13];
    const float* b2      = (const float*)d_in[14];
    const float* lnf_g   = (const float*)d_in[15];
    const float* lnf_b   = (const float*)d_in[16];
    const float* wh      = (const float*)d_in[17];

    int nseq = in_sizes[0] / T_SEQ;
    build_luts<<<1, 512>>>(tok_emb, pos_enc, wq, wk, wv, ln1_g, ln1_b);
    dim3 blk(32, 17);
    tf_main<<<nseq / 32, blk>>>(idx, (float*)d_out, wo, ln2_g, ln2_b,
                                w1, b1, w2, b2, lnf_g, lnf_b, wh);
}

// round 11
// speedup vs baseline: 2.3343x; 1.1431x over previous
#include <cuda_runtime.h>
#include <cuda_bf16.h>

#define T_SEQ 34
#define NTOK  14
#define NE    476   // 34*14 distinct (position, token) variants

typedef unsigned long long u64;
typedef unsigned int       u32;

// LUTs built by prologue kernel (device globals: no allocation allowed)
__device__ float2 g_q[NE * 3];   // prescaled q, packed (head0, head1) per dim
__device__ u64    g_kv[NE * 5];  // bf16x4 per u64; 40B stride => conflict-free banks
__device__ float2 g_x[NE * 3];   // raw embedded x (pre-LN), for residual

// ---------- packed f32x2 helpers (sm_103a) ----------
__device__ __forceinline__ u64 pk2(float a, float b) {
    u64 r; asm("mov.b64 %0,{%1,%2};" : "=l"(r) : "f"(a), "f"(b)); return r;
}
__device__ __forceinline__ u64 pk2f(float2 f) { return pk2(f.x, f.y); }
__device__ __forceinline__ float2 upk2(u64 v) {
    float2 f; asm("mov.b64 {%0,%1},%2;" : "=f"(f.x), "=f"(f.y) : "l"(v)); return f;
}
__device__ __forceinline__ u64 rep2(float a) {
    u64 r; asm("mov.b64 %0,{%1,%1};" : "=l"(r) : "f"(a)); return r;
}
__device__ __forceinline__ u64 fma2(u64 a, u64 b, u64 c) {
    u64 d; asm("fma.rn.f32x2 %0,%1,%2,%3;" : "=l"(d) : "l"(a), "l"(b), "l"(c)); return d;
}
__device__ __forceinline__ u64 add2(u64 a, u64 b) {
    u64 d; asm("add.rn.f32x2 %0,%1,%2;" : "=l"(d) : "l"(a), "l"(b)); return d;
}
__device__ __forceinline__ u64 mul2(u64 a, u64 b) {
    u64 d; asm("mul.rn.f32x2 %0,%1,%2;" : "=l"(d) : "l"(a), "l"(b)); return d;
}
// bf16x2 (lo=head0, hi=head1) -> f32x2
__device__ __forceinline__ u64 bfpair(u32 u) {
    u32 lo = u << 16, hi = u & 0xffff0000u;
    u64 r; asm("mov.b64 %0,{%1,%2};" : "=l"(r) : "r"(lo), "r"(hi)); return r;
}
__device__ __forceinline__ float fex2(float x) { float r; asm("ex2.approx.f32 %0,%1;" : "=f"(r) : "f"(x)); return r; }
__device__ __forceinline__ float frcp(float x) { float r; asm("rcp.approx.f32 %0,%1;" : "=f"(r) : "f"(x)); return r; }
__device__ __forceinline__ float frsq(float x) { float r; asm("rsqrt.approx.f32 %0,%1;" : "=f"(r) : "f"(x)); return r; }

__device__ __forceinline__ unsigned short bfb(float f) {
    return __bfloat16_as_ushort(__float2bfloat16_rn(f));
}

// ---------- prologue: build 476-entry LUTs ----------
__global__ void build_luts(const float* __restrict__ tok_emb, const float* __restrict__ pos_enc,
                           const float* __restrict__ wq, const float* __restrict__ wk,
                           const float* __restrict__ wv,
                           const float* __restrict__ g1, const float* __restrict__ b1) {
    int e = blockIdx.x * blockDim.x + threadIdx.x;
    if (e >= NE) return;
    int t = e / NTOK, c = e % NTOK;
    float x[6];
    x[0] = tok_emb[c * 3 + 0]; x[1] = tok_emb[c * 3 + 1]; x[2] = tok_emb[c * 3 + 2];
    x[3] = pos_enc[t * 3 + 0]; x[4] = pos_enc[t * 3 + 1]; x[5] = pos_enc[t * 3 + 2];
    float s = 0.f;
#pragma unroll
    for (int i = 0; i < 6; i++) s += x[i];
    float mu = s * (1.f / 6.f);
    float v = 0.f;
#pragma unroll
    for (int i = 0; i < 6; i++) { float d = x[i] - mu; v += d * d; }
    v *= (1.f / 6.f);
    float r = frsq(v + 1e-5f);
    float n[6];
#pragma unroll
    for (int i = 0; i < 6; i++) n[i] = (x[i] - mu) * r * g1[i] + b1[i];

    float q[6], k[6], vv[6];  // index = h*3+d
#pragma unroll
    for (int j = 0; j < 6; j++) {
        q[j]  = n[3] * wq[j] + n[4] * wq[6 + j] + n[5] * wq[12 + j];
        k[j]  = n[3] * wk[j] + n[4] * wk[6 + j] + n[5] * wk[12 + j];
        vv[j] = n[0] * wv[j] + n[1] * wv[6 + j] + n[2] * wv[12 + j];
    }
    // fold 1/sqrt(HEAD_DIM) and log2(e) into q (inner loop uses ex2)
    const float qs = 1.4426950408889634f * 0.57735026918962576f;
    float2* qp = g_q + e * 3;
#pragma unroll
    for (int d = 0; d < 3; d++) qp[d] = make_float2(q[d] * qs, q[3 + d] * qs);

    u32 w[6];
#pragma unroll
    for (int d = 0; d < 3; d++) {
        w[d]     = ((u32)bfb(k[3 + d])  << 16) | (u32)bfb(k[d]);
        w[3 + d] = ((u32)bfb(vv[3 + d]) << 16) | (u32)bfb(vv[d]);
    }
    u64* kvp = g_kv + e * 5;
    kvp[0] = ((u64)w[1] << 32) | w[0];
    kvp[1] = ((u64)w[3] << 32) | w[2];
    kvp[2] = ((u64)w[5] << 32) | w[4];
    kvp[3] = 0;
    kvp[4] = 0;

    float2* xp = g_x + e * 3;
    xp[0] = make_float2(x[0], x[1]);
    xp[1] = make_float2(x[2], x[3]);
    xp[2] = make_float2(x[4], x[5]);
}

// ---------- per-token layernorm over 6 dims ----------
__device__ __forceinline__ void ln6(const float* x, float* o, const float* g, const float* b) {
    float s = 0.f;
#pragma unroll
    for (int i = 0; i < 6; i++) s += x[i];
    float mu = s * (1.f / 6.f);
    float v = 0.f;
#pragma unroll
    for (int i = 0; i < 6; i++) { float d = x[i] - mu; v += d * d; }
    v *= (1.f / 6.f);
    float r = frsq(v + 1e-5f);
#pragma unroll
    for (int i = 0; i < 6; i++) o[i] = (x[i] - mu) * r * g[i] + b[i];
}

__device__ __forceinline__ float gelu_exact(float x) {
    return 0.5f * x * (1.f + erff(x * 0.70710678118654752f));
}

// ---------- per-token epilogue (weights re-read via broadcast LDS) ----------
__device__ __forceinline__ void epi_token(const float* __restrict__ o,
                                          const float2* __restrict__ xr,
                                          const float* __restrict__ sw,
                                          float* __restrict__ outp) {
    const u64* woP = (const u64*)sw;            // rows j: woP[j*4 + p], p<3
    const u64* w1P = (const u64*)(sw + 48);
    const u64* w2P = (const u64*)(sw + 96);
    const u64* whP = (const u64*)(sw + 144);    // rows i: whP[i*8 + p], p<7
    const u64* b1P = (const u64*)(sw + 240);
    const u64* b2P = (const u64*)(sw + 248);

    // residual + attention out projection
    u64 x1[3] = { pk2f(xr[0]), pk2f(xr[1]), pk2f(xr[2]) };
#pragma unroll
    for (int j = 0; j < 6; j++) {
        u64 oa = rep2(o[j]);
        x1[0] = fma2(oa, woP[j * 4],     x1[0]);
        x1[1] = fma2(oa, woP[j * 4 + 1], x1[1]);
        x1[2] = fma2(oa, woP[j * 4 + 2], x1[2]);
    }
    float xa[6];
#pragma unroll
    for (int p = 0; p < 3; p++) { float2 f = upk2(x1[p]); xa[2 * p] = f.x; xa[2 * p + 1] = f.y; }

    float ha[6];
    ln6(xa, ha, sw + 256, sw + 264);

    u64 ff[3] = { b1P[0], b1P[1], b1P[2] };
#pragma unroll
    for (int i = 0; i < 6; i++) {
        u64 va = rep2(ha[i]);
        ff[0] = fma2(va, w1P[i * 4],     ff[0]);
        ff[1] = fma2(va, w1P[i * 4 + 1], ff[1]);
        ff[2] = fma2(va, w1P[i * 4 + 2], ff[2]);
    }
    float g[6];
#pragma unroll
    for (int p = 0; p < 3; p++) {
        float2 f = upk2(ff[p]);
        g[2 * p] = gelu_exact(f.x); g[2 * p + 1] = gelu_exact(f.y);
    }
    u64 x2[3];
#pragma unroll
    for (int p = 0; p < 3; p++) x2[p] = add2(x1[p], b2P[p]);
#pragma unroll
    for (int j = 0; j < 6; j++) {
        u64 va = rep2(g[j]);
        x2[0] = fma2(va, w2P[j * 4],     x2[0]);
        x2[1] = fma2(va, w2P[j * 4 + 1], x2[1]);
        x2[2] = fma2(va, w2P[j * 4 + 2], x2[2]);
    }
    float ta[6], ya[6];
#pragma unroll
    for (int p = 0; p < 3; p++) { float2 f = upk2(x2[p]); ta[2 * p] = f.x; ta[2 * p + 1] = f.y; }
    ln6(ta, ya, sw + 272, sw + 280);

    u64 la[7] = {0, 0, 0, 0, 0, 0, 0};
#pragma unroll
    for (int i = 0; i < 6; i++) {
        u64 va = rep2(ya[i]);
#pragma unroll
        for (int p = 0; p < 7; p++) la[p] = fma2(va, whP[i * 8 + p], la[p]);
    }
    u64* op = (u64*)outp;
#pragma unroll
    for (int p = 0; p < 7; p++) op[p] = la[p];
}

// ---------- ONE token end-to-end (low register footprint: ~40 live regs) ----------
__device__ __forceinline__ void attn_one(int t, int lane, int seq,
                                         const float2* __restrict__ sh_q,
                                         const u64* __restrict__ sh_kv,
                                         const float2* __restrict__ sh_x,
                                         const int* __restrict__ sh_off,
                                         const float* __restrict__ sw,
                                         float* __restrict__ out) {
    int e = sh_off[t * 32 + lane];

    u64 q[3];
    {
        const float2* p = sh_q + e * 3;
        q[0] = pk2f(p[0]); q[1] = pk2f(p[1]); q[2] = pk2f(p[2]);
    }

    u64 acc[3] = {0, 0, 0};
    u64 den = 0;   // packed (0.f,0.f)

#pragma unroll 2
    for (int k = 0; k <= t; k++) {
        const u64* kp = sh_kv + sh_off[k * 32 + lane] * 5;   // 40B stride: conflict-free
        u64 kv0 = kp[0], kv1 = kp[1], kv2 = kp[2];           // 3x LDS.64
        u64 K0 = bfpair((u32)kv0), K1 = bfpair((u32)(kv0 >> 32)), K2 = bfpair((u32)kv1);
        u64 V0 = bfpair((u32)(kv1 >> 32)), V1 = bfpair((u32)kv2), V2 = bfpair((u32)(kv2 >> 32));

        u64 s = fma2(q[0], K0, fma2(q[1], K1, mul2(q[2], K2)));
        float2 sf = upk2(s);
        u64 w = pk2(fex2(sf.x), fex2(sf.y));
        den = add2(den, w);
        acc[0] = fma2(w, V0, acc[0]);
        acc[1] = fma2(w, V1, acc[1]);
        acc[2] = fma2(w, V2, acc[2]);
    }

    float o[6];   // [h*3+d]
    {
        float2 d = upk2(den); float r0 = frcp(d.x), r1 = frcp(d.y);
#pragma unroll
        for (int j = 0; j < 3; j++) { float2 a = upk2(acc[j]); o[j] = a.x * r0; o[3 + j] = a.y * r1; }
    }

    epi_token(o, sh_x + e * 3, sw, out + (seq * 34 + t) * 14);
}

// ---------- main kernel: 32 sequences/block, 17 warps, warp y does t=y then t=33-y;
//            sequential tokens keep live state ~40 regs -> 2 CTAs/SM without spills ----------
__global__ void __launch_bounds__(544, 2)
tf_main(const int* __restrict__ idx, float* __restrict__ out,
        const float* __restrict__ wo, const float* __restrict__ g2, const float* __restrict__ bb2,
        const float* __restrict__ w1, const float* __restrict__ b1v,
        const float* __restrict__ w2, const float* __restrict__ b2v,
        const float* __restrict__ gf, const float* __restrict__ bfv,
        const float* __restrict__ wh) {
    __shared__ float2 sh_q[NE * 3];
    __shared__ u64    sh_kv[NE * 5];
    __shared__ float2 sh_x[NE * 3];
    __shared__ int    sh_off[T_SEQ * 32];
    __shared__ __align__(16) float sw[288];

    const int NT = 544;
    int tid = threadIdx.y * 32 + threadIdx.x;
    int base = blockIdx.x * 32;

    for (int i = tid; i < NE * 3; i += NT) {
        sh_q[i] = g_q[i];
        sh_x[i] = g_x[i];
    }
    for (int i = tid; i < NE * 5; i += NT) sh_kv[i] = g_kv[i];
    for (int i = tid; i < 288; i += NT) sw[i] = 0.f;
    for (int i = tid; i < T_SEQ * 32; i += NT) {
        int k = i >> 5, ln = i & 31;
        sh_off[i] = k * NTOK + idx[(base + ln) * T_SEQ + k];  // raw LUT entry index
    }
    __syncthreads();
    // structured weight fill (padding already zeroed)
    if (tid < 36)       { sw[(tid / 6) * 8 + tid % 6] = wo[tid]; }
    else if (tid < 72)  { int i = tid - 36;  sw[48  + (i / 6) * 8  + i % 6]  = w1[i]; }
    else if (tid < 108) { int i = tid - 72;  sw[96  + (i / 6) * 8  + i % 6]  = w2[i]; }
    else if (tid < 192) { int i = tid - 108; sw[144 + (i / 14) * 16 + i % 14] = wh[i]; }
    else if (tid < 198) { sw[240 + tid - 192] = b1v[tid - 192]; }
    else if (tid < 204) { sw[248 + tid - 198] = b2v[tid - 198]; }
    else if (tid < 210) { sw[256 + tid - 204] = g2[tid - 204]; }
    else if (tid < 216) { sw[264 + tid - 210] = bb2[tid - 210]; }
    else if (tid < 222) { sw[272 + tid - 216] = gf[tid - 216]; }
    else if (tid < 228) { sw[280 + tid - 222] = bfv[tid - 222]; }
    __syncthreads();

    int lane = threadIdx.x, y = threadIdx.y;
    int seq = base + lane;

    attn_one(y, lane, seq, sh_q, sh_kv, sh_x, sh_off, sw, out);
    __syncwarp();   // keep token-2 state out of token-1's live range
    attn_one(33 - y, lane, seq, sh_q, sh_kv, sh_x, sh_off, sw, out);
}

extern "C" void kernel_launch(void* const* d_in, const int* in_sizes, int n_in,
                              void* d_out, int out_size) {
    const int*   idx     = (const int*)d_in[0];
    const float* tok_emb = (const float*)d_in[1];
    const float* pos_enc = (const float*)d_in[2];
    const float* wq      = (const float*)d_in[3];
    const float* wk      = (const float*)d_in[4];
    const float* wv      = (const float*)d_in[5];
    const float* wo      = (const float*)d_in[6];
    const float* ln1_g   = (const float*)d_in[7];
    const float* ln1_b   = (const float*)d_in[8];
    const float* ln2_g   = (const float*)d_in[9];
    const float* ln2_b   = (const float*)d_in[10];
    const float* w1      = (const float*)d_in[11];
    const float* b1      = (const float*)d_in[12];
    const float* w2      = (const float*)d_in[13];
    const float* b2      = (const float*)d_in[14];
    const float* lnf_g   = (const float*)d_in[15];
    const float* lnf_b   = (const float*)d_in[16];
    const float* wh      = (const float*)d_in[17];

    int nseq = in_sizes[0] / T_SEQ;
    build_luts<<<1, 512>>>(tok_emb, pos_enc, wq, wk, wv, ln1_g, ln1_b);
    dim3 blk(32, 17);
    tf_main<<<nseq / 32, blk>>>(idx, (float*)d_out, wo, ln2_g, ln2_b,
                                w1, b1, w2, b2, lnf_g, lnf_b, wh);
}

// round 12
// speedup vs baseline: 2.6419x; 1.1318x over previous
#include <cuda_runtime.h>
#include <cuda_bf16.h>

#define T_SEQ 34
#define NTOK  14
#define NE    476   // 34*14 distinct (position, token) variants

typedef unsigned long long u64;
typedef unsigned int       u32;

// LUTs built by prologue kernel (device globals: no allocation allowed)
__device__ float2 g_q[NE * 3];   // prescaled q, packed (head0, head1) per dim
__device__ u64    g_kv[NE * 5];  // bf16x4 per u64; 40B stride => conflict-free banks
__device__ float2 g_x[NE * 3];   // raw embedded x (pre-LN), for residual
__device__ float  g_sw[288];     // staged epilogue weights (padded layout)

// epilogue weights in constant memory: uniform loads go through the const port,
// NOT the shared-memory crossbar (which the attention loop saturates)
__constant__ __align__(16) float c_sw[288];

// ---------- packed f32x2 helpers (sm_103a) ----------
__device__ __forceinline__ u64 pk2(float a, float b) {
    u64 r; asm("mov.b64 %0,{%1,%2};" : "=l"(r) : "f"(a), "f"(b)); return r;
}
__device__ __forceinline__ u64 pk2f(float2 f) { return pk2(f.x, f.y); }
__device__ __forceinline__ float2 upk2(u64 v) {
    float2 f; asm("mov.b64 {%0,%1},%2;" : "=f"(f.x), "=f"(f.y) : "l"(v)); return f;
}
__device__ __forceinline__ u64 rep2(float a) {
    u64 r; asm("mov.b64 %0,{%1,%1};" : "=l"(r) : "f"(a)); return r;
}
__device__ __forceinline__ u64 fma2(u64 a, u64 b, u64 c) {
    u64 d; asm("fma.rn.f32x2 %0,%1,%2,%3;" : "=l"(d) : "l"(a), "l"(b), "l"(c)); return d;
}
__device__ __forceinline__ u64 add2(u64 a, u64 b) {
    u64 d; asm("add.rn.f32x2 %0,%1,%2;" : "=l"(d) : "l"(a), "l"(b)); return d;
}
__device__ __forceinline__ u64 mul2(u64 a, u64 b) {
    u64 d; asm("mul.rn.f32x2 %0,%1,%2;" : "=l"(d) : "l"(a), "l"(b)); return d;
}
// bf16x2 (lo=head0, hi=head1) -> f32x2
__device__ __forceinline__ u64 bfpair(u32 u) {
    u32 lo = u << 16, hi = u & 0xffff0000u;
    u64 r; asm("mov.b64 %0,{%1,%2};" : "=l"(r) : "r"(lo), "r"(hi)); return r;
}
__device__ __forceinline__ float fex2(float x) { float r; asm("ex2.approx.f32 %0,%1;" : "=f"(r) : "f"(x)); return r; }
__device__ __forceinline__ float frcp(float x) { float r; asm("rcp.approx.f32 %0,%1;" : "=f"(r) : "f"(x)); return r; }
__device__ __forceinline__ float frsq(float x) { float r; asm("rsqrt.approx.f32 %0,%1;" : "=f"(r) : "f"(x)); return r; }

__device__ __forceinline__ unsigned short bfb(float f) {
    return __bfloat16_as_ushort(__float2bfloat16_rn(f));
}

// const-space u64 fetch (off = float index, must be even)
__device__ __forceinline__ u64 cld(int off) {
    return *reinterpret_cast<const u64*>(c_sw + off);
}

// ---------- prologue: build 476-entry LUTs + stage epilogue weight block ----------
__global__ void build_luts(const float* __restrict__ tok_emb, const float* __restrict__ pos_enc,
                           const float* __restrict__ wq, const float* __restrict__ wk,
                           const float* __restrict__ wv,
                           const float* __restrict__ g1, const float* __restrict__ b1,
                           const float* __restrict__ wo, const float* __restrict__ w1,
                           const float* __restrict__ b1v, const float* __restrict__ w2,
                           const float* __restrict__ b2v, const float* __restrict__ g2,
                           const float* __restrict__ bb2, const float* __restrict__ gf,
                           const float* __restrict__ bfv, const float* __restrict__ wh) {
    int e = blockIdx.x * blockDim.x + threadIdx.x;

    // ---- stage epilogue weights (padded layout) ----
    if (e < 288) {
        int s = e; float val = 0.f;
        if (s < 48)       { int r = s >> 3, c = s & 7;                 if (c < 6)  val = wo[r * 6 + c]; }
        else if (s < 96)  { int s2 = s - 48;  int r = s2 >> 3, c = s2 & 7;  if (c < 6)  val = w1[r * 6 + c]; }
        else if (s < 144) { int s2 = s - 96;  int r = s2 >> 3, c = s2 & 7;  if (c < 6)  val = w2[r * 6 + c]; }
        else if (s < 240) { int s2 = s - 144; int r = s2 >> 4, c = s2 & 15; if (c < 14) val = wh[r * 14 + c]; }
        else if (s < 248) { int c = s - 240; if (c < 6) val = b1v[c]; }
        else if (s < 256) { int c = s - 248; if (c < 6) val = b2v[c]; }
        else if (s < 264) { int c = s - 256; if (c < 6) val = g2[c]; }
        else if (s < 272) { int c = s - 264; if (c < 6) val = bb2[c]; }
        else if (s < 280) { int c = s - 272; if (c < 6) val = gf[c]; }
        else              { int c = s - 280; if (c < 6) val = bfv[c]; }
        g_sw[s] = val;
    }

    if (e >= NE) return;
    int t = e / NTOK, c = e % NTOK;
    float x[6];
    x[0] = tok_emb[c * 3 + 0]; x[1] = tok_emb[c * 3 + 1]; x[2] = tok_emb[c * 3 + 2];
    x[3] = pos_enc[t * 3 + 0]; x[4] = pos_enc[t * 3 + 1]; x[5] = pos_enc[t * 3 + 2];
    float s = 0.f;
#pragma unroll
    for (int i = 0; i < 6; i++) s += x[i];
    float mu = s * (1.f / 6.f);
    float v = 0.f;
#pragma unroll
    for (int i = 0; i < 6; i++) { float d = x[i] - mu; v += d * d; }
    v *= (1.f / 6.f);
    float r = frsq(v + 1e-5f);
    float n[6];
#pragma unroll
    for (int i = 0; i < 6; i++) n[i] = (x[i] - mu) * r * g1[i] + b1[i];

    float q[6], k[6], vv[6];  // index = h*3+d
#pragma unroll
    for (int j = 0; j < 6; j++) {
        q[j]  = n[3] * wq[j] + n[4] * wq[6 + j] + n[5] * wq[12 + j];
        k[j]  = n[3] * wk[j] + n[4] * wk[6 + j] + n[5] * wk[12 + j];
        vv[j] = n[0] * wv[j] + n[1] * wv[6 + j] + n[2] * wv[12 + j];
    }
    // fold 1/sqrt(HEAD_DIM) and log2(e) into q (inner loop uses ex2)
    const float qs = 1.4426950408889634f * 0.57735026918962576f;
    float2* qp = g_q + e * 3;
#pragma unroll
    for (int d = 0; d < 3; d++) qp[d] = make_float2(q[d] * qs, q[3 + d] * qs);

    u32 w[6];
#pragma unroll
    for (int d = 0; d < 3; d++) {
        w[d]     = ((u32)bfb(k[3 + d])  << 16) | (u32)bfb(k[d]);
        w[3 + d] = ((u32)bfb(vv[3 + d]) << 16) | (u32)bfb(vv[d]);
    }
    u64* kvp = g_kv + e * 5;
    kvp[0] = ((u64)w[1] << 32) | w[0];
    kvp[1] = ((u64)w[3] << 32) | w[2];
    kvp[2] = ((u64)w[5] << 32) | w[4];
    kvp[3] = 0;
    kvp[4] = 0;

    float2* xp = g_x + e * 3;
    xp[0] = make_float2(x[0], x[1]);
    xp[1] = make_float2(x[2], x[3]);
    xp[2] = make_float2(x[4], x[5]);
}

// ---------- per-token layernorm over 6 dims, gamma/beta from const memory ----------
template<int GO, int BO>
__device__ __forceinline__ void ln6c(const float* x, float* o) {
    float s = 0.f;
#pragma unroll
    for (int i = 0; i < 6; i++) s += x[i];
    float mu = s * (1.f / 6.f);
    float v = 0.f;
#pragma unroll
    for (int i = 0; i < 6; i++) { float d = x[i] - mu; v += d * d; }
    v *= (1.f / 6.f);
    float r = frsq(v + 1e-5f);
#pragma unroll
    for (int i = 0; i < 6; i++) o[i] = (x[i] - mu) * r * c_sw[GO + i] + c_sw[BO + i];
}

__device__ __forceinline__ float gelu_exact(float x) {
    return 0.5f * x * (1.f + erff(x * 0.70710678118654752f));
}

// ---------- per-token epilogue: all weights via const port (no LDS traffic) ----------
__device__ __forceinline__ void epi_token(const float* __restrict__ o,
                                          const float2* __restrict__ xr,
                                          float* __restrict__ outp) {
    // residual + attention out projection
    u64 x1[3] = { pk2f(xr[0]), pk2f(xr[1]), pk2f(xr[2]) };
#pragma unroll
    for (int j = 0; j < 6; j++) {
        u64 oa = rep2(o[j]);
        x1[0] = fma2(oa, cld(j * 8 + 0), x1[0]);
        x1[1] = fma2(oa, cld(j * 8 + 2), x1[1]);
        x1[2] = fma2(oa, cld(j * 8 + 4), x1[2]);
    }
    float xa[6];
#pragma unroll
    for (int p = 0; p < 3; p++) { float2 f = upk2(x1[p]); xa[2 * p] = f.x; xa[2 * p + 1] = f.y; }

    float ha[6];
    ln6c<256, 264>(xa, ha);

    u64 ff[3] = { cld(240), cld(242), cld(244) };
#pragma unroll
    for (int i = 0; i < 6; i++) {
        u64 va = rep2(ha[i]);
        ff[0] = fma2(va, cld(48 + i * 8 + 0), ff[0]);
        ff[1] = fma2(va, cld(48 + i * 8 + 2), ff[1]);
        ff[2] = fma2(va, cld(48 + i * 8 + 4), ff[2]);
    }
    float g[6];
#pragma unroll
    for (int p = 0; p < 3; p++) {
        float2 f = upk2(ff[p]);
        g[2 * p] = gelu_exact(f.x); g[2 * p + 1] = gelu_exact(f.y);
    }
    u64 x2[3];
#pragma unroll
    for (int p = 0; p < 3; p++) x2[p] = add2(x1[p], cld(248 + 2 * p));
#pragma unroll
    for (int j = 0; j < 6; j++) {
        u64 va = rep2(g[j]);
        x2[0] = fma2(va, cld(96 + j * 8 + 0), x2[0]);
        x2[1] = fma2(va, cld(96 + j * 8 + 2), x2[1]);
        x2[2] = fma2(va, cld(96 + j * 8 + 4), x2[2]);
    }
    float ta[6], ya[6];
#pragma unroll
    for (int p = 0; p < 3; p++) { float2 f = upk2(x2[p]); ta[2 * p] = f.x; ta[2 * p + 1] = f.y; }
    ln6c<272, 280>(ta, ya);

    u64 la[7] = {0, 0, 0, 0, 0, 0, 0};
#pragma unroll
    for (int i = 0; i < 6; i++) {
        u64 va = rep2(ya[i]);
#pragma unroll
        for (int p = 0; p < 7; p++) la[p] = fma2(va, cld(144 + i * 16 + 2 * p), la[p]);
    }
    u64* op = (u64*)outp;
#pragma unroll
    for (int p = 0; p < 7; p++) op[p] = la[p];
}

// ---------- ONE token end-to-end (low register footprint) ----------
__device__ __forceinline__ void attn_one(int t, int lane, int seq,
                                         const float2* __restrict__ sh_q,
                                         const u64* __restrict__ sh_kv,
                                         const float2* __restrict__ sh_x,
                                         const int* __restrict__ sh_off,
                                         float* __restrict__ out) {
    int e = sh_off[t * 32 + lane];

    u64 q[3];
    {
        const float2* p = sh_q + e * 3;
        q[0] = pk2f(p[0]); q[1] = pk2f(p[1]); q[2] = pk2f(p[2]);
    }

    u64 acc[3] = {0, 0, 0};
    u64 den = 0;   // packed (0.f,0.f)

#pragma unroll 2
    for (int k = 0; k <= t; k++) {
        const u64* kp = sh_kv + sh_off[k * 32 + lane] * 5;   // 40B stride: conflict-free
        u64 kv0 = kp[0], kv1 = kp[1], kv2 = kp[2];           // 3x LDS.64
        u64 K0 = bfpair((u32)kv0), K1 = bfpair((u32)(kv0 >> 32)), K2 = bfpair((u32)kv1);
        u64 V0 = bfpair((u32)(kv1 >> 32)), V1 = bfpair((u32)kv2), V2 = bfpair((u32)(kv2 >> 32));

        u64 s = fma2(q[0], K0, fma2(q[1], K1, mul2(q[2], K2)));
        float2 sf = upk2(s);
        u64 w = pk2(fex2(sf.x), fex2(sf.y));
        den = add2(den, w);
        acc[0] = fma2(w, V0, acc[0]);
        acc[1] = fma2(w, V1, acc[1]);
        acc[2] = fma2(w, V2, acc[2]);
    }

    float o[6];   // [h*3+d]
    {
        float2 d = upk2(den); float r0 = frcp(d.x), r1 = frcp(d.y);
#pragma unroll
        for (int j = 0; j < 3; j++) { float2 a = upk2(acc[j]); o[j] = a.x * r0; o[3 + j] = a.y * r1; }
    }

    epi_token(o, sh_x + e * 3, out + (seq * 34 + t) * 14);
}

// ---------- main kernel: 32 sequences/block, 17 warps, warp y does t=y then t=33-y ----------
__global__ void __launch_bounds__(544, 2)
tf_main(const int* __restrict__ idx, float* __restrict__ out) {
    __shared__ float2 sh_q[NE * 3];
    __shared__ u64    sh_kv[NE * 5];
    __shared__ float2 sh_x[NE * 3];
    __shared__ int    sh_off[T_SEQ * 32];

    const int NT = 544;
    int tid = threadIdx.y * 32 + threadIdx.x;
    int base = blockIdx.x * 32;

    for (int i = tid; i < NE * 3; i += NT) {
        sh_q[i] = g_q[i];
        sh_x[i] = g_x[i];
    }
    for (int i = tid; i < NE * 5; i += NT) sh_kv[i] = g_kv[i];
    for (int i = tid; i < T_SEQ * 32; i += NT) {
        int k = i >> 5, ln = i & 31;
        sh_off[i] = k * NTOK + idx[(base + ln) * T_SEQ + k];  // raw LUT entry index
    }
    __syncthreads();

    int lane = threadIdx.x, y = threadIdx.y;
    int seq = base + lane;

    attn_one(y, lane, seq, sh_q, sh_kv, sh_x, sh_off, out);
    __syncwarp();   // keep token-2 state out of token-1's live range
    attn_one(33 - y, lane, seq, sh_q, sh_kv, sh_x, sh_off, out);
}

extern "C" void kernel_launch(void* const* d_in, const int* in_sizes, int n_in,
                              void* d_out, int out_size) {
    const int*   idx     = (const int*)d_in[0];
    const float* tok_emb = (const float*)d_in[1];
    const float* pos_enc = (const float*)d_in[2];
    const float* wq      = (const float*)d_in[3];
    const float* wk      = (const float*)d_in[4];
    const float* wv      = (const float*)d_in[5];
    const float* wo      = (const float*)d_in[6];
    const float* ln1_g   = (const float*)d_in[7];
    const float* ln1_b   = (const float*)d_in[8];
    const float* ln2_g   = (const float*)d_in[9];
    const float* ln2_b   = (const float*)d_in[10];
    const float* w1      = (const float*)d_in[11];
    const float* b1      = (const float*)d_in[12];
    const float* w2      = (const float*)d_in[13];
    const float* b2      = (const float*)d_in[14];
    const float* lnf_g   = (const float*)d_in[15];
    const float* lnf_b   = (const float*)d_in[16];
    const float* wh      = (const float*)d_in[17];

    int nseq = in_sizes[0] / T_SEQ;

    build_luts<<<1, 512>>>(tok_emb, pos_enc, wq, wk, wv, ln1_g, ln1_b,
                           wo, w1, b1, w2, b2, ln2_g, ln2_b, lnf_g, lnf_b, wh);

    // copy staged weight block into constant memory (D2D memcpy: graph-capturable)
    void *c_addr = nullptr, *s_addr = nullptr;
    cudaGetSymbolAddress(&c_addr, c_sw);
    cudaGetSymbolAddress(&s_addr, g_sw);
    cudaMemcpyAsync(c_addr, s_addr, 288 * sizeof(float), cudaMemcpyDeviceToDevice);

    dim3 blk(32, 17);
    tf_main<<<nseq / 32, blk>>>(idx, (float*)d_out);
}